// round 5
// baseline (speedup 1.0000x reference)
#include <cuda_runtime.h>
#include <cstdint>
#include <cmath>

#define N0 4096
#define MASK0 (N0 - 1)

// ---------------- static device scratch (sanctioned workaround) ----------------
__device__ float2 g_buf[(size_t)N0 * N0];   // Mallat-layout coefficient image
__device__ float2 g_tmp[(size_t)N0 * N0];   // intermediate after one axis

// db4 analysis filters (float32, matching reference; hi[k] = (-1)^k lo[7-k])
__constant__ float c_lo[8] = {
    -0.010597401784997278f, 0.032883011666982945f, 0.030841381835986965f,
    -0.18703481171888114f, -0.02798376941698385f, 0.6308807679295904f,
    0.7148465705525415f, 0.23037781330885523f};
__constant__ float c_hi[8] = {
    0.23037781330885523f, -0.7148465705525415f, 0.6308807679295904f,
    0.02798376941698385f, -0.18703481171888114f, -0.030841381835986965f,
    0.032883011666982945f, 0.010597401784997278f};

#define THRESH 0.005f

__device__ __forceinline__ float2 soft_thresh(float2 v) {
    float mag = sqrtf(v.x * v.x + v.y * v.y);
    float s = (mag > THRESH) ? (1.0f - THRESH / mag) : 0.0f;
    return make_float2(v.x * s, v.y * s);
}

// ---------------- forward horizontal (axis 1) analysis ----------------
// a[m] = sum_k lo[k] x[(2m+k) mod n]; writes A | D halves of g_tmp rows.
// FIRST: gather from the two input planes with the circular roll folded in.
template <bool FIRST>
__global__ void fwd_h(const float* __restrict__ xr, const float* __restrict__ xi,
                      int n, int shift) {
    __shared__ float2 sX[4][136];
    const int nm = n - 1;
    const int m0 = blockIdx.x * 64;
    const int r = (blockIdx.y * 4 + threadIdx.y) & nm;
    const int tx = threadIdx.x;

    for (int t = tx; t < 135; t += 64) {
        int col = (2 * m0 + t) & nm;           // masked: always in [0, n)
        float2 v;
        if (FIRST) {
            int cc = (col - shift) & MASK0;
            int rr = (r - shift) & MASK0;
            v.x = xr[rr * N0 + cc];
            v.y = xi[rr * N0 + cc];
        } else {
            v = g_buf[(size_t)r * N0 + col];
        }
        sX[threadIdx.y][t] = v;
    }
    __syncthreads();

    float2 a = make_float2(0.f, 0.f), d = make_float2(0.f, 0.f);
#pragma unroll
    for (int k = 0; k < 8; k++) {
        float2 v = sX[threadIdx.y][2 * tx + k];   // max 133 < 136
        a.x += c_lo[k] * v.x; a.y += c_lo[k] * v.y;
        d.x += c_hi[k] * v.x; d.y += c_hi[k] * v.y;
    }
    const int m = (m0 + tx) & nm;
    g_tmp[(size_t)r * N0 + m] = a;
    g_tmp[(size_t)r * N0 + ((m + (n >> 1)) & nm)] = d;
}

// ---------------- forward vertical (axis 0) analysis + threshold ----------------
__global__ void fwd_v(int n, int thresh_all) {
    const int nm = n - 1;
    const int h = n >> 1;
    const int hm = h - 1;
    const int c = (blockIdx.x * 64 + threadIdx.x) & nm;
    const int m = (blockIdx.y * 4 + threadIdx.y) & hm;
    float2 a = make_float2(0.f, 0.f), d = make_float2(0.f, 0.f);
#pragma unroll
    for (int k = 0; k < 8; k++) {
        int rr = (2 * m + k) & nm;
        float2 v = g_tmp[(size_t)rr * N0 + c];
        a.x += c_lo[k] * v.x; a.y += c_lo[k] * v.y;
        d.x += c_hi[k] * v.x; d.y += c_hi[k] * v.y;
    }
    if (thresh_all || c >= h) a = soft_thresh(a);   // LL untouched except deepest level
    d = soft_thresh(d);
    g_buf[(size_t)m * N0 + c] = a;
    g_buf[(size_t)(m + h) * N0 + c] = d;
}

// ---------------- inverse vertical synthesis ----------------
// x[i] = sum_k lo[k] a_up[(i-k) mod n] + hi[k] d_up[(i-k) mod n], a_up[2m]=a[m]
__global__ void inv_v(int n) {
    const int nm = n - 1;
    const int h = n >> 1;
    const int c = (blockIdx.x * 64 + threadIdx.x) & nm;
    const int i = (blockIdx.y * 4 + threadIdx.y) & nm;
    const int p = i & 1;
    float2 s = make_float2(0.f, 0.f);
#pragma unroll
    for (int j = 0; j < 4; j++) {
        int k = 2 * j + p;                    // parity of i: only even (i-k) survive
        int m = ((i - k) & nm) >> 1;          // in [0, h)
        float2 av = g_buf[(size_t)m * N0 + c];
        float2 dv = g_buf[(size_t)(m + h) * N0 + c];
        s.x += c_lo[k] * av.x + c_hi[k] * dv.x;
        s.y += c_lo[k] * av.y + c_hi[k] * dv.y;
    }
    g_tmp[(size_t)i * N0 + c] = s;
}

// ---------------- inverse horizontal synthesis ----------------
// MODE 0: scratch write to g_buf (intermediate levels)
// MODE 1: final, interleaved complex floats (re,im pairs), bounds-guarded
// MODE 2: final, real part only, bounds-guarded
template <int MODE>
__global__ void inv_h(float* __restrict__ out, int n, int shift,
                      size_t cap_floats) {
    __shared__ float2 sA[2][68];
    __shared__ float2 sD[2][68];
    const int nm = n - 1;
    const int h = n >> 1;
    const int hm = h - 1;
    const int j0 = blockIdx.x * 128;
    const int r = (blockIdx.y * 2 + threadIdx.y) & nm;
    const int tx = threadIdx.x;
    const int mbase = (j0 >> 1) - 4;

    for (int t = tx; t < 68; t += 128) {
        int m = (mbase + t) & hm;             // masked circular
        sA[threadIdx.y][t] = g_tmp[(size_t)r * N0 + m];
        sD[threadIdx.y][t] = g_tmp[(size_t)r * N0 + m + h];
    }
    __syncthreads();

    const int p = tx & 1;
    float2 s = make_float2(0.f, 0.f);
#pragma unroll
    for (int j = 0; j < 4; j++) {
        int k = 2 * j + p;
        int t = ((tx - k) >> 1) + 4;          // static range [0, 68)
        float2 av = sA[threadIdx.y][t];
        float2 dv = sD[threadIdx.y][t];
        s.x += c_lo[k] * av.x + c_hi[k] * dv.x;
        s.y += c_lo[k] * av.y + c_hi[k] * dv.y;
    }
    const int jg = (j0 + tx) & nm;
    if (MODE == 0) {
        g_buf[(size_t)r * N0 + jg] = s;
    } else {
        int oc = (jg - shift) & MASK0;
        int orow = (r - shift) & MASK0;
        size_t idx = (size_t)orow * N0 + oc;
        if (MODE == 1) {
            size_t o = idx * 2;
            if (o + 1 < cap_floats) {         // proven-safe store
                out[o] = s.x;
                out[o + 1] = s.y;
            }
        } else {                              // MODE == 2: real plane only
            if (idx < cap_floats) out[idx] = s.x;
        }
    }
}

// ---------------- host: numpy default_rng(1000).uniform(-3,3) ----------------
// SeedSequence(1000) pool mix + generate_state(4, uint64) -> PCG64 (XSL-RR 128/64).
static int compute_shift() {
    const uint32_t INIT_A = 0x43b0d7e5u, MULT_A = 0x931e8875u;
    const uint32_t INIT_B = 0x8b51f9ddu, MULT_B = 0x58f38dedu;
    const uint32_t MIX_L = 0xca01f9ddu, MIX_R = 0x4973f715u;

    uint32_t hc = INIT_A;
    auto hashmix = [&](uint32_t v) -> uint32_t {
        v ^= hc; hc *= MULT_A; v *= hc; v ^= v >> 16; return v;
    };
    auto mix = [&](uint32_t x, uint32_t y) -> uint32_t {
        uint32_t r = MIX_L * x; r ^= MIX_R * y; r ^= r >> 16; return r;
    };

    uint32_t pool[4];
    for (int i = 0; i < 4; i++) pool[i] = hashmix(i == 0 ? 1000u : 0u);
    for (int s = 0; s < 4; s++)
        for (int d = 0; d < 4; d++)
            if (s != d) pool[d] = mix(pool[d], hashmix(pool[s]));

    uint32_t hb = INIT_B;
    uint32_t st[8];
    for (int i = 0; i < 8; i++) {
        uint32_t v = pool[i % 4];
        v ^= hb; hb *= MULT_B; v *= hb; v ^= v >> 16;
        st[i] = v;
    }
    uint64_t w[4];
    for (int i = 0; i < 4; i++)
        w[i] = (uint64_t)st[2 * i] | ((uint64_t)st[2 * i + 1] << 32);

    __uint128_t initstate = ((__uint128_t)w[0] << 64) | w[1];
    __uint128_t initseq = ((__uint128_t)w[2] << 64) | w[3];
    const __uint128_t MULT =
        ((__uint128_t)0x2360ed051fc65da4ULL << 64) | 0x4385df649fccf645ULL;

    __uint128_t inc = (initseq << 1) | 1;
    __uint128_t state = 0;
    state = state * MULT + inc;    // seeding step 1
    state += initstate;
    state = state * MULT + inc;    // seeding step 2
    state = state * MULT + inc;    // first next64: step, then output
    uint64_t xored = (uint64_t)(state >> 64) ^ (uint64_t)state;
    unsigned rot = (unsigned)(state >> 122) & 63u;
    uint64_t r64 = (xored >> rot) | (xored << ((64u - rot) & 63u));
    double dbl = (double)(r64 >> 11) * (1.0 / 9007199254740992.0);
    double u = -3.0 + 6.0 * dbl;
    return (int)nearbyint(u);      // round-half-even, same as Python round()
}

// ---------------- launch ----------------
extern "C" void kernel_launch(void* const* d_in, const int* in_sizes, int n_in,
                              void* d_out, int out_size) {
    if (n_in < 2) return;                                  // -> "0 nodes" diagnostic
    if (in_sizes[0] < N0 * N0 || in_sizes[1] < N0 * N0) return;
    const float* xr = (const float*)d_in[0];
    const float* xi = (const float*)d_in[1];
    float* out = (float*)d_out;

    const size_t cap = (size_t)out_size;                   // elements of output dtype
    const bool interleaved = cap >= (size_t)2 * N0 * N0;   // float32-view complex layout
    const int shift = compute_shift();
    const dim3 b64x4(64, 4);
    const dim3 b128x2(128, 2);

    // forward: 4 levels (phase drops out analytically; roll folded into level 0)
    for (int l = 0; l < 4; l++) {
        int n = N0 >> l;
        dim3 gh((n / 2) / 64, n / 4);
        if (l == 0)
            fwd_h<true><<<gh, b64x4>>>(xr, xi, n, shift);
        else
            fwd_h<false><<<gh, b64x4>>>(xr, xi, n, shift);
        dim3 gv(n / 64, (n / 2) / 4);
        fwd_v<<<gv, b64x4>>>(n, (l == 3) ? 1 : 0);
    }

    // inverse: deepest level first
    for (int l = 3; l >= 0; l--) {
        int n = N0 >> l;
        dim3 gv(n / 64, n / 4);
        inv_v<<<gv, b64x4>>>(n);
        dim3 gh(n / 128, n / 2);
        if (l > 0) {
            inv_h<0><<<gh, b128x2>>>(out, n, shift, cap);
        } else if (interleaved) {
            inv_h<1><<<gh, b128x2>>>(out, n, shift, cap);
        } else {
            inv_h<2><<<gh, b128x2>>>(out, n, shift, cap);
        }
    }
}

// round 6
// speedup vs baseline: 1.4280x; 1.4280x over previous
#include <cuda_runtime.h>
#include <cstdint>
#include <cmath>

#define N0 4096
#define MASK0 (N0 - 1)
typedef unsigned long long u64;

// ---------------- static device scratch ----------------
__device__ u64 g_coef[(size_t)N0 * N0];                 // detail coeffs, Mallat positions
__device__ u64 g_imgA[(size_t)(N0 / 2) * (N0 / 2)];     // ping (holds up to 2048^2)
__device__ u64 g_imgB[(size_t)(N0 / 4) * (N0 / 4)];     // pong (holds up to 1024^2)

__constant__ float c_lo[8] = {
    -0.010597401784997278f, 0.032883011666982945f, 0.030841381835986965f,
    -0.18703481171888114f, -0.02798376941698385f, 0.6308807679295904f,
    0.7148465705525415f, 0.23037781330885523f};
__constant__ float c_hi[8] = {
    0.23037781330885523f, -0.7148465705525415f, 0.6308807679295904f,
    0.02798376941698385f, -0.18703481171888114f, -0.030841381835986965f,
    0.032883011666982945f, 0.010597401784997278f};

#define THRESH 0.005f

union U64F2 { u64 u; float2 f; };

__device__ __forceinline__ u64 pk2(float v) {
    u64 r; asm("mov.b64 %0, {%1, %1};" : "=l"(r) : "f"(v)); return r;
}
__device__ __forceinline__ u64 pkf2(float x, float y) {
    u64 r; asm("mov.b64 %0, {%1, %2};" : "=l"(r) : "f"(x), "f"(y)); return r;
}
// packed complex FMA: acc += c * v on both lanes (re,im)
__device__ __forceinline__ void fma2(u64& acc, u64 c, u64 v) {
    asm("fma.rn.f32x2 %0, %1, %2, %0;" : "+l"(acc) : "l"(c), "l"(v));
}
__device__ __forceinline__ u64 soft2(u64 v) {
    U64F2 u; u.u = v;
    float mag = sqrtf(u.f.x * u.f.x + u.f.y * u.f.y);
    float s = (mag > THRESH) ? (1.0f - THRESH / mag) : 0.0f;
    u.f.x *= s; u.f.y *= s;
    return u.u;
}
__device__ __forceinline__ u64* imgp(int s) { return s ? g_imgB : g_imgA; }

// ================= fused forward level (H analysis + V analysis + threshold) =================
// Tile: 16 (m) x 32 (mc) quadrant outputs per block; input region 38 x 70.
template <bool FIRST>
__global__ void __launch_bounds__(256) fwd_fused(
    const float* __restrict__ xr, const float* __restrict__ xi,
    int n, int shift, int src_sel, int dst_sel, int thresh_all)
{
    __shared__ u64 sE[38][37], sO[38][37];   // parity-split input (even/odd cols)
    __shared__ u64 sA[38][33], sD[38][33];   // horizontal a/d

    const int tid = threadIdx.x;
    const int nm = n - 1;
    const int h = n >> 1, hm = h - 1;
    const int m0 = blockIdx.y * 16;
    const int c0 = blockIdx.x * 32;
    const int row0 = 2 * m0;
    const int col0 = 2 * c0;
    const u64* src = imgp(src_sel);

    // ---- stage 1: load input tile (roll folded in at level 0) ----
    for (int idx = tid; idx < 38 * 70; idx += 256) {
        int row = idx / 70, col = idx - row * 70;
        int gr = (row0 + row) & nm;
        int gc = (col0 + col) & nm;
        u64 v;
        if (FIRST) {
            int rr = (gr - shift) & MASK0;
            int cc = (gc - shift) & MASK0;
            v = pkf2(xr[rr * N0 + cc], xi[rr * N0 + cc]);
        } else {
            v = src[(size_t)gr * n + gc];
        }
        if (col & 1) sO[row][col >> 1] = v; else sE[row][col >> 1] = v;
    }
    __syncthreads();

    u64 lo2[8], hi2[8];
#pragma unroll
    for (int k = 0; k < 8; k++) { lo2[k] = pk2(c_lo[k]); hi2[k] = pk2(c_hi[k]); }

    // ---- stage 2: horizontal analysis (conflict-free parity reads) ----
    for (int idx = tid; idx < 38 * 32; idx += 256) {
        int j = idx >> 5, t = idx & 31;
        u64 a = 0, d = 0;
#pragma unroll
        for (int q = 0; q < 4; q++) {
            u64 e = sE[j][t + q], o = sO[j][t + q];
            fma2(a, lo2[2 * q], e); fma2(a, lo2[2 * q + 1], o);
            fma2(d, hi2[2 * q], e); fma2(d, hi2[2 * q + 1], o);
        }
        sA[j][t] = a; sD[j][t] = d;
    }
    __syncthreads();

    // ---- stage 3: vertical analysis (2-row coarsened), threshold, store ----
    {
        const int mc = tid & 31;
        const int mg = (tid >> 5) << 1;         // 0,2,...,14
        u64 rA[10], rD[10];
#pragma unroll
        for (int w = 0; w < 10; w++) { rA[w] = sA[2 * mg + w][mc]; rD[w] = sD[2 * mg + w][mc]; }
        u64 ll0 = 0, lh0 = 0, hl0 = 0, hh0 = 0, ll1 = 0, lh1 = 0, hl1 = 0, hh1 = 0;
#pragma unroll
        for (int k = 0; k < 8; k++) {
            fma2(ll0, lo2[k], rA[k]);     fma2(hl0, hi2[k], rA[k]);
            fma2(lh0, lo2[k], rD[k]);     fma2(hh0, hi2[k], rD[k]);
            fma2(ll1, lo2[k], rA[k + 2]); fma2(hl1, hi2[k], rA[k + 2]);
            fma2(lh1, lo2[k], rD[k + 2]); fma2(hh1, hi2[k], rD[k + 2]);
        }
        u64* dst = imgp(dst_sel);
        const int mcg = (c0 + mc) & hm;
        const int mA = (m0 + mg) & hm;
        const int mB = (m0 + mg + 1) & hm;
        dst[(size_t)mA * h + mcg] = thresh_all ? soft2(ll0) : ll0;
        dst[(size_t)mB * h + mcg] = thresh_all ? soft2(ll1) : ll1;
        g_coef[(size_t)mA * N0 + h + mcg] = soft2(lh0);
        g_coef[(size_t)mB * N0 + h + mcg] = soft2(lh1);
        g_coef[(size_t)(mA + h) * N0 + mcg] = soft2(hl0);
        g_coef[(size_t)(mB + h) * N0 + mcg] = soft2(hl1);
        g_coef[(size_t)(mA + h) * N0 + h + mcg] = soft2(hh0);
        g_coef[(size_t)(mB + h) * N0 + h + mcg] = soft2(hh1);
    }
}

// ================= fused inverse level (H synthesis + V synthesis) =================
// Tile: 32 (i) x 64 (jj) output pixels; coeff region 19 x 35 per quadrant.
// MODE 0: write recon image to img buffer. MODE 1: final interleaved complex out.
// MODE 2: final real-plane out.
template <int MODE>
__global__ void __launch_bounds__(256) inv_fused(
    void* outp, int n, int shift, int ll_sel, int dst_sel, size_t cap)
{
    __shared__ u64 sLL[19][36], sLH[19][36], sHL[19][36], sHH[19][36];
    __shared__ u64 sAq[19][65], sDq[19][65];

    const int tid = threadIdx.x;
    const int nm = n - 1;
    const int h = n >> 1, hm = h - 1;
    const int i0 = blockIdx.y * 32;
    const int j0 = blockIdx.x * 64;
    const int mb = (i0 >> 1) - 3;
    const int cb = (j0 >> 1) - 3;
    const u64* llsrc = imgp(ll_sel);

    // ---- stage 1: load 4 coefficient quadrants ----
    for (int idx = tid; idx < 19 * 35; idx += 256) {
        int row = idx / 35, col = idx - row * 35;
        int m = (mb + row) & hm;
        int mc = (cb + col) & hm;
        sLL[row][col] = llsrc[(size_t)m * h + mc];
        sLH[row][col] = g_coef[(size_t)m * N0 + h + mc];
        sHL[row][col] = g_coef[(size_t)(m + h) * N0 + mc];
        sHH[row][col] = g_coef[(size_t)(m + h) * N0 + h + mc];
    }
    __syncthreads();

    u64 lo2[8], hi2[8];
#pragma unroll
    for (int k = 0; k < 8; k++) { lo2[k] = pk2(c_lo[k]); hi2[k] = pk2(c_hi[k]); }

    // ---- stage 2: horizontal synthesis ----
    for (int idx = tid; idx < 19 * 64; idx += 256) {
        int mrow = idx >> 6, jjp = idx & 63;
        int p = jjp & 1;
        int jb = (jjp >> 1) + 3;
        u64 cl[4], ch[4];
#pragma unroll
        for (int q = 0; q < 4; q++) {
            cl[q] = p ? lo2[2 * q + 1] : lo2[2 * q];
            ch[q] = p ? hi2[2 * q + 1] : hi2[2 * q];
        }
        u64 a = 0, d = 0;
#pragma unroll
        for (int q = 0; q < 4; q++) {
            int ci = jb - q;
            fma2(a, cl[q], sLL[mrow][ci]); fma2(a, ch[q], sLH[mrow][ci]);
            fma2(d, cl[q], sHL[mrow][ci]); fma2(d, ch[q], sHH[mrow][ci]);
        }
        sAq[mrow][jjp] = a; sDq[mrow][jjp] = d;
    }
    __syncthreads();

    // ---- stage 3: vertical synthesis (2-row pairs), write ----
    for (int idx = tid; idx < 1024; idx += 256) {
        int jj = idx & 63;
        int g = idx >> 6;                // 0..15
        int ig = g << 1;
        u64 e = 0, o = 0;
#pragma unroll
        for (int w = 0; w < 4; w++) {
            u64 a = sAq[g + w][jj], d = sDq[g + w][jj];
            fma2(e, lo2[6 - 2 * w], a); fma2(e, hi2[6 - 2 * w], d);
            fma2(o, lo2[7 - 2 * w], a); fma2(o, hi2[7 - 2 * w], d);
        }
        int gi0 = i0 + ig, gi1 = gi0 + 1;
        int gj = j0 + jj;
        if (MODE == 0) {
            u64* dst = imgp(dst_sel);
            dst[(size_t)(gi0 & nm) * n + (gj & nm)] = e;
            dst[(size_t)(gi1 & nm) * n + (gj & nm)] = o;
        } else if (MODE == 1) {
            u64* out64 = (u64*)outp;
            int oc = (gj - shift) & MASK0;
            size_t p0 = (size_t)((gi0 - shift) & MASK0) * N0 + oc;
            size_t p1 = (size_t)((gi1 - shift) & MASK0) * N0 + oc;
            if (p0 < cap) out64[p0] = e;    // cap in u64 units
            if (p1 < cap) out64[p1] = o;
        } else {
            float* outf = (float*)outp;
            int oc = (gj - shift) & MASK0;
            size_t p0 = (size_t)((gi0 - shift) & MASK0) * N0 + oc;
            size_t p1 = (size_t)((gi1 - shift) & MASK0) * N0 + oc;
            U64F2 ue, uo; ue.u = e; uo.u = o;
            if (p0 < cap) outf[p0] = ue.f.x;  // cap in floats
            if (p1 < cap) outf[p1] = uo.f.x;
        }
    }
}

// ---------------- host: numpy default_rng(1000).uniform(-3,3) ----------------
static int compute_shift() {
    const uint32_t INIT_A = 0x43b0d7e5u, MULT_A = 0x931e8875u;
    const uint32_t INIT_B = 0x8b51f9ddu, MULT_B = 0x58f38dedu;
    const uint32_t MIX_L = 0xca01f9ddu, MIX_R = 0x4973f715u;

    uint32_t hc = INIT_A;
    auto hashmix = [&](uint32_t v) -> uint32_t {
        v ^= hc; hc *= MULT_A; v *= hc; v ^= v >> 16; return v;
    };
    auto mix = [&](uint32_t x, uint32_t y) -> uint32_t {
        uint32_t r = MIX_L * x; r ^= MIX_R * y; r ^= r >> 16; return r;
    };

    uint32_t pool[4];
    for (int i = 0; i < 4; i++) pool[i] = hashmix(i == 0 ? 1000u : 0u);
    for (int s = 0; s < 4; s++)
        for (int d = 0; d < 4; d++)
            if (s != d) pool[d] = mix(pool[d], hashmix(pool[s]));

    uint32_t hb = INIT_B;
    uint32_t st[8];
    for (int i = 0; i < 8; i++) {
        uint32_t v = pool[i % 4];
        v ^= hb; hb *= MULT_B; v *= hb; v ^= v >> 16;
        st[i] = v;
    }
    uint64_t w[4];
    for (int i = 0; i < 4; i++)
        w[i] = (uint64_t)st[2 * i] | ((uint64_t)st[2 * i + 1] << 32);

    __uint128_t initstate = ((__uint128_t)w[0] << 64) | w[1];
    __uint128_t initseq = ((__uint128_t)w[2] << 64) | w[3];
    const __uint128_t MULT =
        ((__uint128_t)0x2360ed051fc65da4ULL << 64) | 0x4385df649fccf645ULL;

    __uint128_t inc = (initseq << 1) | 1;
    __uint128_t state = 0;
    state = state * MULT + inc;
    state += initstate;
    state = state * MULT + inc;
    state = state * MULT + inc;
    uint64_t xored = (uint64_t)(state >> 64) ^ (uint64_t)state;
    unsigned rot = (unsigned)(state >> 122) & 63u;
    uint64_t r64 = (xored >> rot) | (xored << ((64u - rot) & 63u));
    double dbl = (double)(r64 >> 11) * (1.0 / 9007199254740992.0);
    double u = -3.0 + 6.0 * dbl;
    return (int)nearbyint(u);
}

// ---------------- launch ----------------
extern "C" void kernel_launch(void* const* d_in, const int* in_sizes, int n_in,
                              void* d_out, int out_size) {
    if (n_in < 2) return;
    if (in_sizes[0] < N0 * N0 || in_sizes[1] < N0 * N0) return;
    const float* xr = (const float*)d_in[0];
    const float* xi = (const float*)d_in[1];

    const size_t capf = (size_t)out_size;
    const bool inter = capf >= (size_t)2 * N0 * N0;
    const int shift = compute_shift();
    const dim3 blk(256);

    // forward: LL ping-pong A(l0) -> B(l1) -> A(l2) -> B(l3, thresholded)
    const int fsrc[4] = {0, 0, 1, 0};
    const int fdst[4] = {0, 1, 0, 1};
    for (int l = 0; l < 4; l++) {
        int n = N0 >> l, h = n >> 1;
        dim3 grid(h / 32, h / 16);
        if (l == 0)
            fwd_fused<true><<<grid, blk>>>(xr, xi, n, shift, 0, fdst[0], 0);
        else
            fwd_fused<false><<<grid, blk>>>(xr, xi, n, shift, fsrc[l], fdst[l],
                                            (l == 3) ? 1 : 0);
    }

    // inverse: LL src B(256^2) -> recon A(512^2) -> B(1024^2) -> A(2048^2) -> out
    const int llsel[4] = {0, 1, 0, 1};   // indexed by level
    const int dsel[4]  = {0, 0, 1, 0};
    for (int l = 3; l >= 0; l--) {
        int n = N0 >> l;
        dim3 grid(n / 64, n / 32);
        if (l > 0)
            inv_fused<0><<<grid, blk>>>(nullptr, n, shift, llsel[l], dsel[l], 0);
        else if (inter)
            inv_fused<1><<<grid, blk>>>(d_out, n, shift, llsel[0], 0, capf / 2);
        else
            inv_fused<2><<<grid, blk>>>(d_out, n, shift, llsel[0], 0, capf);
    }
}

// round 7
// speedup vs baseline: 1.5154x; 1.0612x over previous
#include <cuda_runtime.h>
#include <cstdint>
#include <cmath>

#define N0 4096
#define MASK0 (N0 - 1)
typedef unsigned long long u64;

// ---------------- static device scratch ----------------
__device__ u64 g_coef[(size_t)N0 * N0];                 // detail coeffs, Mallat positions
__device__ u64 g_imgA[(size_t)2048 * 2048];             // ping
__device__ u64 g_imgB[(size_t)1024 * 1024];             // pong

__device__ unsigned g_bar_count;                        // zero-init; self-resetting
__device__ volatile unsigned g_bar_gen;                 // monotonic generation

__constant__ float c_lo[8] = {
    -0.010597401784997278f, 0.032883011666982945f, 0.030841381835986965f,
    -0.18703481171888114f, -0.02798376941698385f, 0.6308807679295904f,
    0.7148465705525415f, 0.23037781330885523f};
__constant__ float c_hi[8] = {
    0.23037781330885523f, -0.7148465705525415f, 0.6308807679295904f,
    0.02798376941698385f, -0.18703481171888114f, -0.030841381835986965f,
    0.032883011666982945f, 0.010597401784997278f};

#define THRESH 0.005f

union U64F2 { u64 u; float2 f; };

__device__ __forceinline__ u64 pk2(float v) {
    u64 r; asm("mov.b64 %0, {%1, %1};" : "=l"(r) : "f"(v)); return r;
}
__device__ __forceinline__ u64 pkf2(float x, float y) {
    u64 r; asm("mov.b64 %0, {%1, %2};" : "=l"(r) : "f"(x), "f"(y)); return r;
}
__device__ __forceinline__ void fma2(u64& acc, u64 c, u64 v) {
    asm("fma.rn.f32x2 %0, %1, %2, %0;" : "+l"(acc) : "l"(c), "l"(v));
}
__device__ __forceinline__ u64 soft2(u64 v) {
    U64F2 u; u.u = v;
    float mag = sqrtf(u.f.x * u.f.x + u.f.y * u.f.y);
    float s = (mag > THRESH) ? (1.0f - THRESH / mag) : 0.0f;
    u.f.x *= s; u.f.y *= s;
    return u.u;
}

// ---------------- shared-memory layouts (union: 42.6 KB max) ----------------
struct SmemF { u64 E[38][37], O[38][37], A[38][33], D[38][33]; };
struct SmemI { u64 LL[19][36], LH[19][36], HL[19][36], HH[19][36], Aq[19][65], Dq[19][65]; };
union SmemU { SmemF f; SmemI v; };

// ---------------- grid-wide barrier (all blocks resident by construction) ----------------
__device__ __forceinline__ void grid_barrier() {
    __threadfence();                       // order this thread's stores to L2
    __syncthreads();                       // whole block's stores now fenced
    if (threadIdx.x == 0) {
        unsigned gen = g_bar_gen;
        if (atomicAdd(&g_bar_count, 1u) == gridDim.x - 1) {
            g_bar_count = 0;               // reset BEFORE gen bump
            __threadfence();
            g_bar_gen = gen + 1;
        } else {
            while (g_bar_gen == gen) __nanosleep(64);
        }
    }
    __syncthreads();
}

// ================= forward level: H analysis + V analysis + threshold =================
__device__ __noinline__ void fwd_level(
    const float* __restrict__ xr, const float* __restrict__ xi,
    int n, int shift, const u64* __restrict__ src, u64* __restrict__ dst,
    int thresh_all, int first, SmemF* s)
{
    const int tid = threadIdx.x;
    const int nm = n - 1;
    const int h = n >> 1, hm = h - 1;
    const int ntx = h >> 5;
    const int ntiles = ntx * (h >> 4);

    u64 lo2[8], hi2[8];
#pragma unroll
    for (int k = 0; k < 8; k++) { lo2[k] = pk2(c_lo[k]); hi2[k] = pk2(c_hi[k]); }

    for (int t = blockIdx.x; t < ntiles; t += gridDim.x) {
        const int c0 = (t % ntx) * 32;
        const int m0 = (t / ntx) * 16;
        const int row0 = 2 * m0, col0 = 2 * c0;

        // stage 1: load 38x70 input region (roll folded in at level 0)
        for (int idx = tid; idx < 38 * 70; idx += 256) {
            int row = idx / 70, col = idx - row * 70;
            int gr = (row0 + row) & nm, gc = (col0 + col) & nm;
            u64 v;
            if (first) {
                int rr = (gr - shift) & MASK0, cc = (gc - shift) & MASK0;
                v = pkf2(__ldg(xr + (size_t)rr * N0 + cc),
                         __ldg(xi + (size_t)rr * N0 + cc));
            } else {
                v = __ldcg(src + (size_t)gr * n + gc);   // L2-only: coherence-safe
            }
            if (col & 1) s->O[row][col >> 1] = v; else s->E[row][col >> 1] = v;
        }
        __syncthreads();

        // stage 2: horizontal analysis (parity-split, conflict-free)
        for (int idx = tid; idx < 38 * 32; idx += 256) {
            int j = idx >> 5, tt = idx & 31;
            u64 a = 0, d = 0;
#pragma unroll
            for (int q = 0; q < 4; q++) {
                u64 e = s->E[j][tt + q], o = s->O[j][tt + q];
                fma2(a, lo2[2 * q], e); fma2(a, lo2[2 * q + 1], o);
                fma2(d, hi2[2 * q], e); fma2(d, hi2[2 * q + 1], o);
            }
            s->A[j][tt] = a; s->D[j][tt] = d;
        }
        __syncthreads();

        // stage 3: vertical analysis (2-row coarsened), threshold, store
        {
            const int mc = tid & 31;
            const int mg = (tid >> 5) << 1;
            u64 rA[10], rD[10];
#pragma unroll
            for (int w = 0; w < 10; w++) {
                rA[w] = s->A[2 * mg + w][mc];
                rD[w] = s->D[2 * mg + w][mc];
            }
            u64 ll0 = 0, lh0 = 0, hl0 = 0, hh0 = 0, ll1 = 0, lh1 = 0, hl1 = 0, hh1 = 0;
#pragma unroll
            for (int k = 0; k < 8; k++) {
                fma2(ll0, lo2[k], rA[k]);     fma2(hl0, hi2[k], rA[k]);
                fma2(lh0, lo2[k], rD[k]);     fma2(hh0, hi2[k], rD[k]);
                fma2(ll1, lo2[k], rA[k + 2]); fma2(hl1, hi2[k], rA[k + 2]);
                fma2(lh1, lo2[k], rD[k + 2]); fma2(hh1, hi2[k], rD[k + 2]);
            }
            const int mcg = (c0 + mc) & hm;
            const int mA = (m0 + mg) & hm, mB = (m0 + mg + 1) & hm;
            dst[(size_t)mA * h + mcg] = thresh_all ? soft2(ll0) : ll0;
            dst[(size_t)mB * h + mcg] = thresh_all ? soft2(ll1) : ll1;
            g_coef[(size_t)mA * N0 + h + mcg] = soft2(lh0);
            g_coef[(size_t)mB * N0 + h + mcg] = soft2(lh1);
            g_coef[(size_t)(mA + h) * N0 + mcg] = soft2(hl0);
            g_coef[(size_t)(mB + h) * N0 + mcg] = soft2(hl1);
            g_coef[(size_t)(mA + h) * N0 + h + mcg] = soft2(hh0);
            g_coef[(size_t)(mB + h) * N0 + h + mcg] = soft2(hh1);
        }
        __syncthreads();   // smem safe before next tile
    }
}

// ================= inverse level: H synthesis + V synthesis =================
// outmode 0: scratch; 1: interleaved complex floats; 2: real plane.
__device__ __noinline__ void inv_level(
    int n, int shift, const u64* __restrict__ llsrc, u64* __restrict__ dst,
    void* outp, int outmode, size_t cap, SmemI* s)
{
    const int tid = threadIdx.x;
    const int nm = n - 1;
    const int h = n >> 1, hm = h - 1;
    const int ntx = n >> 6;
    const int ntiles = ntx * (n >> 5);

    u64 lo2[8], hi2[8];
#pragma unroll
    for (int k = 0; k < 8; k++) { lo2[k] = pk2(c_lo[k]); hi2[k] = pk2(c_hi[k]); }

    for (int t = blockIdx.x; t < ntiles; t += gridDim.x) {
        const int j0 = (t % ntx) * 64;
        const int i0 = (t / ntx) * 32;
        const int mb = (i0 >> 1) - 3, cb = (j0 >> 1) - 3;

        // stage 1: load 4 coefficient quadrants (19x35 each)
        for (int idx = tid; idx < 19 * 35; idx += 256) {
            int row = idx / 35, col = idx - row * 35;
            int m = (mb + row) & hm, mc = (cb + col) & hm;
            s->LL[row][col] = __ldcg(llsrc + (size_t)m * h + mc);
            s->LH[row][col] = __ldcg(g_coef + (size_t)m * N0 + h + mc);
            s->HL[row][col] = __ldcg(g_coef + (size_t)(m + h) * N0 + mc);
            s->HH[row][col] = __ldcg(g_coef + (size_t)(m + h) * N0 + h + mc);
        }
        __syncthreads();

        // stage 2: horizontal synthesis
        for (int idx = tid; idx < 19 * 64; idx += 256) {
            int mrow = idx >> 6, jjp = idx & 63;
            int p = jjp & 1, jb = (jjp >> 1) + 3;
            u64 a = 0, d = 0;
#pragma unroll
            for (int q = 0; q < 4; q++) {
                u64 cl = p ? lo2[2 * q + 1] : lo2[2 * q];
                u64 ch = p ? hi2[2 * q + 1] : hi2[2 * q];
                int ci = jb - q;
                fma2(a, cl, s->LL[mrow][ci]); fma2(a, ch, s->LH[mrow][ci]);
                fma2(d, cl, s->HL[mrow][ci]); fma2(d, ch, s->HH[mrow][ci]);
            }
            s->Aq[mrow][jjp] = a; s->Dq[mrow][jjp] = d;
        }
        __syncthreads();

        // stage 3: vertical synthesis (2-row pairs), write
        for (int idx = tid; idx < 1024; idx += 256) {
            int jj = idx & 63, g = idx >> 6, ig = g << 1;
            u64 e = 0, o = 0;
#pragma unroll
            for (int w = 0; w < 4; w++) {
                u64 a = s->Aq[g + w][jj], d = s->Dq[g + w][jj];
                fma2(e, lo2[6 - 2 * w], a); fma2(e, hi2[6 - 2 * w], d);
                fma2(o, lo2[7 - 2 * w], a); fma2(o, hi2[7 - 2 * w], d);
            }
            int gi0 = i0 + ig, gi1 = gi0 + 1, gj = j0 + jj;
            if (outmode == 0) {
                dst[(size_t)(gi0 & nm) * n + (gj & nm)] = e;
                dst[(size_t)(gi1 & nm) * n + (gj & nm)] = o;
            } else if (outmode == 1) {
                u64* o64 = (u64*)outp;
                int oc = (gj - shift) & MASK0;
                size_t p0 = (size_t)((gi0 - shift) & MASK0) * N0 + oc;
                size_t p1 = (size_t)((gi1 - shift) & MASK0) * N0 + oc;
                if (p0 < cap) o64[p0] = e;       // cap in u64 units
                if (p1 < cap) o64[p1] = o;
            } else {
                float* of = (float*)outp;
                int oc = (gj - shift) & MASK0;
                size_t p0 = (size_t)((gi0 - shift) & MASK0) * N0 + oc;
                size_t p1 = (size_t)((gi1 - shift) & MASK0) * N0 + oc;
                U64F2 ue, uo; ue.u = e; uo.u = o;
                if (p0 < cap) of[p0] = ue.f.x;   // cap in floats
                if (p1 < cap) of[p1] = uo.f.x;
            }
        }
        __syncthreads();   // smem safe before next tile
    }
}

// ================= single persistent kernel: all 8 phases =================
__global__ void __launch_bounds__(256, 4) wav_all(
    const float* __restrict__ xr, const float* __restrict__ xi,
    void* outp, int shift, int outmode, size_t cap)
{
    __shared__ SmemU sm;

    fwd_level(xr, xi, 4096, shift, nullptr, g_imgA, 0, 1, &sm.f);
    grid_barrier();
    fwd_level(xr, xi, 2048, shift, g_imgA, g_imgB, 0, 0, &sm.f);
    grid_barrier();
    fwd_level(xr, xi, 1024, shift, g_imgB, g_imgA, 0, 0, &sm.f);
    grid_barrier();
    fwd_level(xr, xi, 512, shift, g_imgA, g_imgB, 1, 0, &sm.f);
    grid_barrier();
    inv_level(512, shift, g_imgB, g_imgA, nullptr, 0, 0, &sm.v);
    grid_barrier();
    inv_level(1024, shift, g_imgA, g_imgB, nullptr, 0, 0, &sm.v);
    grid_barrier();
    inv_level(2048, shift, g_imgB, g_imgA, nullptr, 0, 0, &sm.v);
    grid_barrier();
    inv_level(4096, shift, g_imgA, nullptr, outp, outmode, cap, &sm.v);
}

// ---------------- host: numpy default_rng(1000).uniform(-3,3) ----------------
static int compute_shift() {
    const uint32_t INIT_A = 0x43b0d7e5u, MULT_A = 0x931e8875u;
    const uint32_t INIT_B = 0x8b51f9ddu, MULT_B = 0x58f38dedu;
    const uint32_t MIX_L = 0xca01f9ddu, MIX_R = 0x4973f715u;

    uint32_t hc = INIT_A;
    auto hashmix = [&](uint32_t v) -> uint32_t {
        v ^= hc; hc *= MULT_A; v *= hc; v ^= v >> 16; return v;
    };
    auto mix = [&](uint32_t x, uint32_t y) -> uint32_t {
        uint32_t r = MIX_L * x; r ^= MIX_R * y; r ^= r >> 16; return r;
    };

    uint32_t pool[4];
    for (int i = 0; i < 4; i++) pool[i] = hashmix(i == 0 ? 1000u : 0u);
    for (int s = 0; s < 4; s++)
        for (int d = 0; d < 4; d++)
            if (s != d) pool[d] = mix(pool[d], hashmix(pool[s]));

    uint32_t hb = INIT_B;
    uint32_t st[8];
    for (int i = 0; i < 8; i++) {
        uint32_t v = pool[i % 4];
        v ^= hb; hb *= MULT_B; v *= hb; v ^= v >> 16;
        st[i] = v;
    }
    uint64_t w[4];
    for (int i = 0; i < 4; i++)
        w[i] = (uint64_t)st[2 * i] | ((uint64_t)st[2 * i + 1] << 32);

    __uint128_t initstate = ((__uint128_t)w[0] << 64) | w[1];
    __uint128_t initseq = ((__uint128_t)w[2] << 64) | w[3];
    const __uint128_t MULT =
        ((__uint128_t)0x2360ed051fc65da4ULL << 64) | 0x4385df649fccf645ULL;

    __uint128_t inc = (initseq << 1) | 1;
    __uint128_t state = 0;
    state = state * MULT + inc;
    state += initstate;
    state = state * MULT + inc;
    state = state * MULT + inc;
    uint64_t xored = (uint64_t)(state >> 64) ^ (uint64_t)state;
    unsigned rot = (unsigned)(state >> 122) & 63u;
    uint64_t r64 = (xored >> rot) | (xored << ((64u - rot) & 63u));
    double dbl = (double)(r64 >> 11) * (1.0 / 9007199254740992.0);
    double u = -3.0 + 6.0 * dbl;
    return (int)nearbyint(u);
}

// ---------------- launch ----------------
extern "C" void kernel_launch(void* const* d_in, const int* in_sizes, int n_in,
                              void* d_out, int out_size) {
    if (n_in < 2) return;
    if (in_sizes[0] < N0 * N0 || in_sizes[1] < N0 * N0) return;
    const float* xr = (const float*)d_in[0];
    const float* xi = (const float*)d_in[1];

    const size_t capf = (size_t)out_size;
    const bool inter = capf >= (size_t)2 * N0 * N0;
    const int shift = compute_shift();
    const int outmode = inter ? 1 : 2;
    const size_t cap = inter ? capf / 2 : capf;   // u64 units vs float units

    // 592 blocks @ 4/SM (regs<=64 forced, smem 42.6KB -> 5/SM possible):
    // guaranteed co-resident on >=148 SMs => barrier cannot deadlock.
    wav_all<<<592, 256>>>(xr, xi, d_out, shift, outmode, cap);
}

// round 8
// speedup vs baseline: 1.6091x; 1.0618x over previous
#include <cuda_runtime.h>
#include <cstdint>
#include <cmath>

#define N0 4096
#define MASK0 (N0 - 1)
typedef unsigned long long u64;

// ---------------- static device scratch (16B-aligned for v2.u64 access) ----------------
__device__ __align__(16) u64 g_coef[(size_t)N0 * N0];     // detail coeffs, Mallat positions
__device__ __align__(16) u64 g_imgA[(size_t)2048 * 2048]; // ping
__device__ __align__(16) u64 g_imgB[(size_t)1024 * 1024]; // pong

__device__ unsigned g_bar_count;                          // zero-init; self-resetting
__device__ volatile unsigned g_bar_gen;                   // monotonic generation

__constant__ float c_lo[8] = {
    -0.010597401784997278f, 0.032883011666982945f, 0.030841381835986965f,
    -0.18703481171888114f, -0.02798376941698385f, 0.6308807679295904f,
    0.7148465705525415f, 0.23037781330885523f};
__constant__ float c_hi[8] = {
    0.23037781330885523f, -0.7148465705525415f, 0.6308807679295904f,
    0.02798376941698385f, -0.18703481171888114f, -0.030841381835986965f,
    0.032883011666982945f, 0.010597401784997278f};

#define THRESH 0.005f

union U64F2 { u64 u; float2 f; };

__device__ __forceinline__ u64 pk2(float v) {
    u64 r; asm("mov.b64 %0, {%1, %1};" : "=l"(r) : "f"(v)); return r;
}
__device__ __forceinline__ u64 pkf2(float x, float y) {
    u64 r; asm("mov.b64 %0, {%1, %2};" : "=l"(r) : "f"(x), "f"(y)); return r;
}
__device__ __forceinline__ void fma2(u64& acc, u64 c, u64 v) {
    asm("fma.rn.f32x2 %0, %1, %2, %0;" : "+l"(acc) : "l"(c), "l"(v));
}
__device__ __forceinline__ ulonglong2 ldcg2(const u64* p) {   // 16B L2-only load
    ulonglong2 r;
    asm volatile("ld.global.cg.v2.u64 {%0,%1}, [%2];" : "=l"(r.x), "=l"(r.y) : "l"(p));
    return r;
}
__device__ __forceinline__ u64 soft2(u64 v) {
    U64F2 u; u.u = v;
    float mag = sqrtf(u.f.x * u.f.x + u.f.y * u.f.y);
    float s = (mag > THRESH) ? (1.0f - THRESH / mag) : 0.0f;
    u.f.x *= s; u.f.y *= s;
    return u.u;
}

// ---------------- shared-memory layouts (union: 42.6 KB max) ----------------
struct SmemF { u64 E[38][37], O[38][37], A[38][33], D[38][33]; };
struct SmemI { u64 LL[19][36], LH[19][36], HL[19][36], HH[19][36], Aq[19][66], Dq[19][66]; };
union SmemU { SmemF f; SmemI v; };

// ---------------- grid-wide barrier (all blocks resident by construction) ----------------
__device__ __forceinline__ void grid_barrier() {
    __threadfence();
    __syncthreads();
    if (threadIdx.x == 0) {
        unsigned gen = g_bar_gen;
        if (atomicAdd(&g_bar_count, 1u) == gridDim.x - 1) {
            g_bar_count = 0;
            __threadfence();
            g_bar_gen = gen + 1;
        } else {
            while (g_bar_gen == gen) __nanosleep(64);
        }
    }
    __syncthreads();
}

// ================= forward level: H analysis + V analysis + threshold =================
__device__ __noinline__ void fwd_level(
    const float* __restrict__ xr, const float* __restrict__ xi,
    int n, int shift, const u64* __restrict__ src, u64* __restrict__ dst,
    int thresh_all, int first, SmemF* s)
{
    const int tid = threadIdx.x;
    const int nm = n - 1;
    const int h = n >> 1, hm = h - 1;
    const int ntx = h >> 5;
    const int ntiles = ntx * (h >> 4);

    u64 lo2[8], hi2[8];
#pragma unroll
    for (int k = 0; k < 8; k++) { lo2[k] = pk2(c_lo[k]); hi2[k] = pk2(c_hi[k]); }

    for (int t = blockIdx.x; t < ntiles; t += gridDim.x) {
        const int c0 = (t % ntx) * 32;
        const int m0 = (t / ntx) * 16;
        const int row0 = 2 * m0, col0 = 2 * c0;

        // ---- stage 1: load 38x70 input region into parity-split arrays ----
        if (first) {
            for (int idx = tid; idx < 38 * 70; idx += 256) {
                int row = idx / 70, col = idx - row * 70;
                int gr = (row0 + row) & nm, gc = (col0 + col) & nm;
                int rr = (gr - shift) & MASK0, cc = (gc - shift) & MASK0;
                u64 v = pkf2(__ldg(xr + (size_t)rr * N0 + cc),
                             __ldg(xi + (size_t)rr * N0 + cc));
                if (col & 1) s->O[row][col >> 1] = v; else s->E[row][col >> 1] = v;
            }
        } else {
            // 16B loads: even/odd column pair feeds E/O directly
            for (int idx = tid; idx < 38 * 35; idx += 256) {
                int row = idx / 35, pc = idx - row * 35;
                int gr = (row0 + row) & nm;
                int gc = (col0 + (pc << 1)) & nm;          // even
                ulonglong2 v = ldcg2(src + (size_t)gr * n + gc);
                s->E[row][pc] = v.x;
                s->O[row][pc] = v.y;
            }
        }
        __syncthreads();

        // ---- stage 2: horizontal analysis (parity-split, conflict-free) ----
        for (int idx = tid; idx < 38 * 32; idx += 256) {
            int j = idx >> 5, tt = idx & 31;
            u64 a = 0, d = 0;
#pragma unroll
            for (int q = 0; q < 4; q++) {
                u64 e = s->E[j][tt + q], o = s->O[j][tt + q];
                fma2(a, lo2[2 * q], e); fma2(a, lo2[2 * q + 1], o);
                fma2(d, hi2[2 * q], e); fma2(d, hi2[2 * q + 1], o);
            }
            s->A[j][tt] = a; s->D[j][tt] = d;
        }
        __syncthreads();

        // ---- stage 3: vertical analysis (2-row coarsened), threshold, store ----
        {
            const int mc = tid & 31;
            const int mg = (tid >> 5) << 1;
            u64 rA[10], rD[10];
#pragma unroll
            for (int w = 0; w < 10; w++) {
                rA[w] = s->A[2 * mg + w][mc];
                rD[w] = s->D[2 * mg + w][mc];
            }
            u64 ll0 = 0, lh0 = 0, hl0 = 0, hh0 = 0, ll1 = 0, lh1 = 0, hl1 = 0, hh1 = 0;
#pragma unroll
            for (int k = 0; k < 8; k++) {
                fma2(ll0, lo2[k], rA[k]);     fma2(hl0, hi2[k], rA[k]);
                fma2(lh0, lo2[k], rD[k]);     fma2(hh0, hi2[k], rD[k]);
                fma2(ll1, lo2[k], rA[k + 2]); fma2(hl1, hi2[k], rA[k + 2]);
                fma2(lh1, lo2[k], rD[k + 2]); fma2(hh1, hi2[k], rD[k + 2]);
            }
            const int mcg = (c0 + mc) & hm;
            const int mA = (m0 + mg) & hm, mB = (m0 + mg + 1) & hm;
            dst[(size_t)mA * h + mcg] = thresh_all ? soft2(ll0) : ll0;
            dst[(size_t)mB * h + mcg] = thresh_all ? soft2(ll1) : ll1;
            g_coef[(size_t)mA * N0 + h + mcg] = soft2(lh0);
            g_coef[(size_t)mB * N0 + h + mcg] = soft2(lh1);
            g_coef[(size_t)(mA + h) * N0 + mcg] = soft2(hl0);
            g_coef[(size_t)(mB + h) * N0 + mcg] = soft2(hl1);
            g_coef[(size_t)(mA + h) * N0 + h + mcg] = soft2(hh0);
            g_coef[(size_t)(mB + h) * N0 + h + mcg] = soft2(hh1);
        }
        __syncthreads();
    }
}

// ================= inverse level: H synthesis + V synthesis =================
// outmode 0: scratch; 1: interleaved complex floats; 2: real plane.
__device__ __noinline__ void inv_level(
    int n, int shift, const u64* __restrict__ llsrc, u64* __restrict__ dst,
    void* outp, int outmode, size_t cap, SmemI* s)
{
    const int tid = threadIdx.x;
    const int nm = n - 1;
    const int h = n >> 1, hm = h - 1;
    const int ntx = n >> 6;
    const int ntiles = ntx * (n >> 5);

    u64 lo2[8], hi2[8];
#pragma unroll
    for (int k = 0; k < 8; k++) { lo2[k] = pk2(c_lo[k]); hi2[k] = pk2(c_hi[k]); }

    for (int t = blockIdx.x; t < ntiles; t += gridDim.x) {
        const int j0 = (t % ntx) * 64;
        const int i0 = (t / ntx) * 32;
        const int mb = (i0 >> 1) - 3;
        const int cbm1 = (j0 >> 1) - 4;     // even column origin (cb - 1)

        // ---- stage 1: load 4 quadrants, 19 rows x 18 col-pairs, 16B ops ----
        for (int idx = tid; idx < 19 * 18; idx += 256) {
            int row = idx / 18, pc = idx - row * 18;
            int m = (mb + row) & hm;
            int mc = (cbm1 + (pc << 1)) & hm;              // even
            ulonglong2 vll = ldcg2(llsrc + (size_t)m * h + mc);
            ulonglong2 vlh = ldcg2(g_coef + (size_t)m * N0 + h + mc);
            ulonglong2 vhl = ldcg2(g_coef + (size_t)(m + h) * N0 + mc);
            ulonglong2 vhh = ldcg2(g_coef + (size_t)(m + h) * N0 + h + mc);
            *(ulonglong2*)&s->LL[row][2 * pc] = vll;
            *(ulonglong2*)&s->LH[row][2 * pc] = vlh;
            *(ulonglong2*)&s->HL[row][2 * pc] = vhl;
            *(ulonglong2*)&s->HH[row][2 * pc] = vhh;
        }
        __syncthreads();

        // ---- stage 2: horizontal synthesis, PAIR-coarsened (jjp=2u,2u+1 share window) ----
        for (int idx = tid; idx < 19 * 32; idx += 256) {
            int mrow = idx >> 5, u = idx & 31;
            u64 ae = 0, ao = 0, de = 0, dq = 0;
#pragma unroll
            for (int q = 0; q < 4; q++) {
                int ci = u + 4 - q;                        // shifted origin: +1
                u64 vLL = s->LL[mrow][ci], vLH = s->LH[mrow][ci];
                u64 vHL = s->HL[mrow][ci], vHH = s->HH[mrow][ci];
                fma2(ae, lo2[2 * q], vLL);     fma2(ae, hi2[2 * q], vLH);
                fma2(ao, lo2[2 * q + 1], vLL); fma2(ao, hi2[2 * q + 1], vLH);
                fma2(de, lo2[2 * q], vHL);     fma2(de, hi2[2 * q], vHH);
                fma2(dq, lo2[2 * q + 1], vHL); fma2(dq, hi2[2 * q + 1], vHH);
            }
            ulonglong2 va; va.x = ae; va.y = ao;
            ulonglong2 vd; vd.x = de; vd.y = dq;
            *(ulonglong2*)&s->Aq[mrow][2 * u] = va;        // stride 66: 16B aligned
            *(ulonglong2*)&s->Dq[mrow][2 * u] = vd;
        }
        __syncthreads();

        // ---- stage 3: vertical synthesis, row-PAIR coarsened (g2,g2+1 share 3 rows) ----
        for (int idx = tid; idx < 512; idx += 256) {
            int jj = idx & 63, gp = idx >> 6;
            int g2 = gp << 1;
            u64 e0 = 0, o0 = 0, e1 = 0, o1 = 0;
#pragma unroll
            for (int w = 0; w < 5; w++) {
                u64 a = s->Aq[g2 + w][jj], d = s->Dq[g2 + w][jj];
                if (w < 4) {
                    fma2(e0, lo2[6 - 2 * w], a); fma2(e0, hi2[6 - 2 * w], d);
                    fma2(o0, lo2[7 - 2 * w], a); fma2(o0, hi2[7 - 2 * w], d);
                }
                if (w >= 1) {
                    fma2(e1, lo2[8 - 2 * w], a); fma2(e1, hi2[8 - 2 * w], d);
                    fma2(o1, lo2[9 - 2 * w], a); fma2(o1, hi2[9 - 2 * w], d);
                }
            }
            const int gj = j0 + jj;
            const int r0 = i0 + (gp << 2);                 // rows r0..r0+3
            if (outmode == 0) {
                const int gjm = gj & nm;
                dst[(size_t)((r0) & nm) * n + gjm] = e0;
                dst[(size_t)((r0 + 1) & nm) * n + gjm] = o0;
                dst[(size_t)((r0 + 2) & nm) * n + gjm] = e1;
                dst[(size_t)((r0 + 3) & nm) * n + gjm] = o1;
            } else if (outmode == 1) {
                u64* o64 = (u64*)outp;
                int oc = (gj - shift) & MASK0;
                size_t p0 = (size_t)((r0 - shift) & MASK0) * N0 + oc;
                size_t p1 = (size_t)((r0 + 1 - shift) & MASK0) * N0 + oc;
                size_t p2 = (size_t)((r0 + 2 - shift) & MASK0) * N0 + oc;
                size_t p3 = (size_t)((r0 + 3 - shift) & MASK0) * N0 + oc;
                if (p0 < cap) o64[p0] = e0;
                if (p1 < cap) o64[p1] = o0;
                if (p2 < cap) o64[p2] = e1;
                if (p3 < cap) o64[p3] = o1;
            } else {
                float* of = (float*)outp;
                int oc = (gj - shift) & MASK0;
                U64F2 u0, u1, u2, u3;
                u0.u = e0; u1.u = o0; u2.u = e1; u3.u = o1;
                size_t p0 = (size_t)((r0 - shift) & MASK0) * N0 + oc;
                size_t p1 = (size_t)((r0 + 1 - shift) & MASK0) * N0 + oc;
                size_t p2 = (size_t)((r0 + 2 - shift) & MASK0) * N0 + oc;
                size_t p3 = (size_t)((r0 + 3 - shift) & MASK0) * N0 + oc;
                if (p0 < cap) of[p0] = u0.f.x;
                if (p1 < cap) of[p1] = u1.f.x;
                if (p2 < cap) of[p2] = u2.f.x;
                if (p3 < cap) of[p3] = u3.f.x;
            }
        }
        __syncthreads();
    }
}

// ================= single persistent kernel: all 8 phases =================
__global__ void __launch_bounds__(256, 4) wav_all(
    const float* __restrict__ xr, const float* __restrict__ xi,
    void* outp, int shift, int outmode, size_t cap)
{
    __shared__ __align__(16) SmemU sm;

    fwd_level(xr, xi, 4096, shift, nullptr, g_imgA, 0, 1, &sm.f);
    grid_barrier();
    fwd_level(xr, xi, 2048, shift, g_imgA, g_imgB, 0, 0, &sm.f);
    grid_barrier();
    fwd_level(xr, xi, 1024, shift, g_imgB, g_imgA, 0, 0, &sm.f);
    grid_barrier();
    fwd_level(xr, xi, 512, shift, g_imgA, g_imgB, 1, 0, &sm.f);
    grid_barrier();
    inv_level(512, shift, g_imgB, g_imgA, nullptr, 0, 0, &sm.v);
    grid_barrier();
    inv_level(1024, shift, g_imgA, g_imgB, nullptr, 0, 0, &sm.v);
    grid_barrier();
    inv_level(2048, shift, g_imgB, g_imgA, nullptr, 0, 0, &sm.v);
    grid_barrier();
    inv_level(4096, shift, g_imgA, nullptr, outp, outmode, cap, &sm.v);
}

// ---------------- host: numpy default_rng(1000).uniform(-3,3) ----------------
static int compute_shift() {
    const uint32_t INIT_A = 0x43b0d7e5u, MULT_A = 0x931e8875u;
    const uint32_t INIT_B = 0x8b51f9ddu, MULT_B = 0x58f38dedu;
    const uint32_t MIX_L = 0xca01f9ddu, MIX_R = 0x4973f715u;

    uint32_t hc = INIT_A;
    auto hashmix = [&](uint32_t v) -> uint32_t {
        v ^= hc; hc *= MULT_A; v *= hc; v ^= v >> 16; return v;
    };
    auto mix = [&](uint32_t x, uint32_t y) -> uint32_t {
        uint32_t r = MIX_L * x; r ^= MIX_R * y; r ^= r >> 16; return r;
    };

    uint32_t pool[4];
    for (int i = 0; i < 4; i++) pool[i] = hashmix(i == 0 ? 1000u : 0u);
    for (int s = 0; s < 4; s++)
        for (int d = 0; d < 4; d++)
            if (s != d) pool[d] = mix(pool[d], hashmix(pool[s]));

    uint32_t hb = INIT_B;
    uint32_t st[8];
    for (int i = 0; i < 8; i++) {
        uint32_t v = pool[i % 4];
        v ^= hb; hb *= MULT_B; v *= hb; v ^= v >> 16;
        st[i] = v;
    }
    uint64_t w[4];
    for (int i = 0; i < 4; i++)
        w[i] = (uint64_t)st[2 * i] | ((uint64_t)st[2 * i + 1] << 32);

    __uint128_t initstate = ((__uint128_t)w[0] << 64) | w[1];
    __uint128_t initseq = ((__uint128_t)w[2] << 64) | w[3];
    const __uint128_t MULT =
        ((__uint128_t)0x2360ed051fc65da4ULL << 64) | 0x4385df649fccf645ULL;

    __uint128_t inc = (initseq << 1) | 1;
    __uint128_t state = 0;
    state = state * MULT + inc;
    state += initstate;
    state = state * MULT + inc;
    state = state * MULT + inc;
    uint64_t xored = (uint64_t)(state >> 64) ^ (uint64_t)state;
    unsigned rot = (unsigned)(state >> 122) & 63u;
    uint64_t r64 = (xored >> rot) | (xored << ((64u - rot) & 63u));
    double dbl = (double)(r64 >> 11) * (1.0 / 9007199254740992.0);
    double u = -3.0 + 6.0 * dbl;
    return (int)nearbyint(u);
}

// ---------------- launch ----------------
extern "C" void kernel_launch(void* const* d_in, const int* in_sizes, int n_in,
                              void* d_out, int out_size) {
    if (n_in < 2) return;
    if (in_sizes[0] < N0 * N0 || in_sizes[1] < N0 * N0) return;
    const float* xr = (const float*)d_in[0];
    const float* xi = (const float*)d_in[1];

    const size_t capf = (size_t)out_size;
    const bool inter = capf >= (size_t)2 * N0 * N0;
    const int shift = compute_shift();
    const int outmode = inter ? 1 : 2;
    const size_t cap = inter ? capf / 2 : capf;   // u64 units vs float units

    wav_all<<<592, 256>>>(xr, xi, d_out, shift, outmode, cap);
}

// round 12
// speedup vs baseline: 1.6558x; 1.0290x over previous
#include <cuda_runtime.h>
#include <cstdint>
#include <cmath>

#define N0 4096
#define MASK0 (N0 - 1)
typedef unsigned long long u64;

// ---------------- static device scratch (16B-aligned for v2.u64 access) ----------------
__device__ __align__(16) u64 g_coef[(size_t)N0 * N0];     // detail coeffs, Mallat positions
__device__ __align__(16) u64 g_imgA[(size_t)2048 * 2048]; // ping
__device__ __align__(16) u64 g_imgB[(size_t)1024 * 1024]; // pong

__device__ unsigned g_bar_count;                          // zero-init; self-resetting
__device__ volatile unsigned g_bar_gen;                   // monotonic generation

__constant__ float c_lo[8] = {
    -0.010597401784997278f, 0.032883011666982945f, 0.030841381835986965f,
    -0.18703481171888114f, -0.02798376941698385f, 0.6308807679295904f,
    0.7148465705525415f, 0.23037781330885523f};
__constant__ float c_hi[8] = {
    0.23037781330885523f, -0.7148465705525415f, 0.6308807679295904f,
    0.02798376941698385f, -0.18703481171888114f, -0.030841381835986965f,
    0.032883011666982945f, 0.010597401784997278f};

#define THRESH 0.005f

union U64F2 { u64 u; float2 f; };

__device__ __forceinline__ u64 pk2(float v) {
    u64 r; asm("mov.b64 %0, {%1, %1};" : "=l"(r) : "f"(v)); return r;
}
__device__ __forceinline__ u64 pkf2(float x, float y) {
    u64 r; asm("mov.b64 %0, {%1, %2};" : "=l"(r) : "f"(x), "f"(y)); return r;
}
__device__ __forceinline__ void fma2(u64& acc, u64 c, u64 v) {
    asm("fma.rn.f32x2 %0, %1, %2, %0;" : "+l"(acc) : "l"(c), "l"(v));
}
__device__ __forceinline__ ulonglong2 ldcg2(const u64* p) {   // 16B L2-only load
    ulonglong2 r;
    asm volatile("ld.global.cg.v2.u64 {%0,%1}, [%2];" : "=l"(r.x), "=l"(r.y) : "l"(p));
    return r;
}
__device__ __forceinline__ u64 soft2(u64 v) {
    U64F2 u; u.u = v;
    float mag = sqrtf(u.f.x * u.f.x + u.f.y * u.f.y);
    float s = (mag > THRESH) ? (1.0f - THRESH / mag) : 0.0f;
    u.f.x *= s; u.f.y *= s;
    return u.u;
}

// ---------------- shared-memory layouts (even strides: all 16B ops aligned) ----------------
struct SmemF { u64 E[38][38], O[38][38], A[38][34], D[38][34]; };   // 42.75 KB
struct SmemI { u64 LL[19][36], LH[19][36], HL[19][36], HH[19][36], Aq[19][66], Dq[19][66]; };
union SmemU { SmemF f; SmemI v; };

// ---------------- grid-wide barrier (all blocks resident by construction) ----------------
__device__ __forceinline__ void grid_barrier() {
    __threadfence();
    __syncthreads();
    if (threadIdx.x == 0) {
        unsigned gen = g_bar_gen;
        if (atomicAdd(&g_bar_count, 1u) == gridDim.x - 1) {
            g_bar_count = 0;
            __threadfence();
            g_bar_gen = gen + 1;
        } else {
            while (g_bar_gen == gen) __nanosleep(64);
        }
    }
    __syncthreads();
}

// ================= forward level: H analysis + V analysis + threshold =================
__device__ __noinline__ void fwd_level(
    const float* __restrict__ xr, const float* __restrict__ xi,
    int n, int shift, const u64* __restrict__ src, u64* __restrict__ dst,
    int thresh_all, int first, SmemF* s)
{
    const int tid = threadIdx.x;
    const int nm = n - 1;
    const int h = n >> 1, hm = h - 1;
    const int ntx = h >> 5;
    const int ntiles = ntx * (h >> 4);

    u64 lo2[8], hi2[8];
#pragma unroll
    for (int k = 0; k < 8; k++) { lo2[k] = pk2(c_lo[k]); hi2[k] = pk2(c_hi[k]); }

    for (int t = blockIdx.x; t < ntiles; t += gridDim.x) {
        const int c0 = (t % ntx) * 32;
        const int m0 = (t / ntx) * 16;
        const int row0 = 2 * m0, col0 = 2 * c0;

        // ---- stage 1: load 38x70 input region into parity-split arrays ----
        if (first) {
            for (int idx = tid; idx < 38 * 70; idx += 256) {
                int row = idx / 70, col = idx - row * 70;
                int gr = (row0 + row) & nm, gc = (col0 + col) & nm;
                int rr = (gr - shift) & MASK0, cc = (gc - shift) & MASK0;
                u64 v = pkf2(__ldg(xr + (size_t)rr * N0 + cc),
                             __ldg(xi + (size_t)rr * N0 + cc));
                if (col & 1) s->O[row][col >> 1] = v; else s->E[row][col >> 1] = v;
            }
        } else {
            // 16B loads: even/odd column pair feeds E/O directly
            for (int idx = tid; idx < 38 * 35; idx += 256) {
                int row = idx / 35, pc = idx - row * 35;
                int gr = (row0 + row) & nm;
                int gc = (col0 + (pc << 1)) & nm;          // even
                ulonglong2 v = ldcg2(src + (size_t)gr * n + gc);
                s->E[row][pc] = v.x;
                s->O[row][pc] = v.y;
            }
        }
        __syncthreads();

        // ---- stage 2: horizontal analysis, PAIR-coarsened + vectorized ----
        for (int idx = tid; idx < 38 * 16; idx += 256) {
            int j = idx >> 4, u = idx & 15;
            int tt = u << 1;
            ulonglong2 e01 = *(const ulonglong2*)&s->E[j][tt];
            ulonglong2 e23 = *(const ulonglong2*)&s->E[j][tt + 2];
            u64 e4 = s->E[j][tt + 4];
            ulonglong2 o01 = *(const ulonglong2*)&s->O[j][tt];
            ulonglong2 o23 = *(const ulonglong2*)&s->O[j][tt + 2];
            u64 o4 = s->O[j][tt + 4];
            u64 e[5] = {e01.x, e01.y, e23.x, e23.y, e4};
            u64 o[5] = {o01.x, o01.y, o23.x, o23.y, o4};
            u64 a0 = 0, a1 = 0, d0 = 0, d1 = 0;
#pragma unroll
            for (int q = 0; q < 4; q++) {
                fma2(a0, lo2[2 * q], e[q]);     fma2(a0, lo2[2 * q + 1], o[q]);
                fma2(d0, hi2[2 * q], e[q]);     fma2(d0, hi2[2 * q + 1], o[q]);
                fma2(a1, lo2[2 * q], e[q + 1]); fma2(a1, lo2[2 * q + 1], o[q + 1]);
                fma2(d1, hi2[2 * q], e[q + 1]); fma2(d1, hi2[2 * q + 1], o[q + 1]);
            }
            ulonglong2 va; va.x = a0; va.y = a1;
            ulonglong2 vd; vd.x = d0; vd.y = d1;
            *(ulonglong2*)&s->A[j][tt] = va;               // stride 34: aligned
            *(ulonglong2*)&s->D[j][tt] = vd;
        }
        __syncthreads();

        // ---- stage 3: vertical analysis (2-row coarsened), threshold, store ----
        {
            const int mc = tid & 31;
            const int mg = (tid >> 5) << 1;
            u64 rA[10], rD[10];
#pragma unroll
            for (int w = 0; w < 10; w++) {
                rA[w] = s->A[2 * mg + w][mc];
                rD[w] = s->D[2 * mg + w][mc];
            }
            u64 ll0 = 0, lh0 = 0, hl0 = 0, hh0 = 0, ll1 = 0, lh1 = 0, hl1 = 0, hh1 = 0;
#pragma unroll
            for (int k = 0; k < 8; k++) {
                fma2(ll0, lo2[k], rA[k]);     fma2(hl0, hi2[k], rA[k]);
                fma2(lh0, lo2[k], rD[k]);     fma2(hh0, hi2[k], rD[k]);
                fma2(ll1, lo2[k], rA[k + 2]); fma2(hl1, hi2[k], rA[k + 2]);
                fma2(lh1, lo2[k], rD[k + 2]); fma2(hh1, hi2[k], rD[k + 2]);
            }
            const int mcg = (c0 + mc) & hm;
            const int mA = (m0 + mg) & hm, mB = (m0 + mg + 1) & hm;
            dst[(size_t)mA * h + mcg] = thresh_all ? soft2(ll0) : ll0;
            dst[(size_t)mB * h + mcg] = thresh_all ? soft2(ll1) : ll1;
            g_coef[(size_t)mA * N0 + h + mcg] = soft2(lh0);
            g_coef[(size_t)mB * N0 + h + mcg] = soft2(lh1);
            g_coef[(size_t)(mA + h) * N0 + mcg] = soft2(hl0);
            g_coef[(size_t)(mB + h) * N0 + mcg] = soft2(hl1);
            g_coef[(size_t)(mA + h) * N0 + h + mcg] = soft2(hh0);
            g_coef[(size_t)(mB + h) * N0 + h + mcg] = soft2(hh1);
        }
        __syncthreads();
    }
}

// ================= inverse level: H synthesis + V synthesis =================
// outmode 0: scratch; 1: interleaved complex floats; 2: real plane.
__device__ __noinline__ void inv_level(
    int n, int shift, const u64* __restrict__ llsrc, u64* __restrict__ dst,
    void* outp, int outmode, size_t cap, SmemI* s)
{
    const int tid = threadIdx.x;
    const int nm = n - 1;
    const int h = n >> 1, hm = h - 1;
    const int ntx = n >> 6;
    const int ntiles = ntx * (n >> 5);

    u64 lo2[8], hi2[8];
#pragma unroll
    for (int k = 0; k < 8; k++) { lo2[k] = pk2(c_lo[k]); hi2[k] = pk2(c_hi[k]); }

    for (int t = blockIdx.x; t < ntiles; t += gridDim.x) {
        const int j0 = (t % ntx) * 64;
        const int i0 = (t / ntx) * 32;
        const int mb = (i0 >> 1) - 3;
        const int cbm1 = (j0 >> 1) - 4;     // even column origin (cb - 1)

        // ---- stage 1: load 4 quadrants, 19 rows x 18 col-pairs, 16B ops ----
        for (int idx = tid; idx < 19 * 18; idx += 256) {
            int row = idx / 18, pc = idx - row * 18;
            int m = (mb + row) & hm;
            int mc = (cbm1 + (pc << 1)) & hm;              // even
            ulonglong2 vll = ldcg2(llsrc + (size_t)m * h + mc);
            ulonglong2 vlh = ldcg2(g_coef + (size_t)m * N0 + h + mc);
            ulonglong2 vhl = ldcg2(g_coef + (size_t)(m + h) * N0 + mc);
            ulonglong2 vhh = ldcg2(g_coef + (size_t)(m + h) * N0 + h + mc);
            *(ulonglong2*)&s->LL[row][2 * pc] = vll;
            *(ulonglong2*)&s->LH[row][2 * pc] = vlh;
            *(ulonglong2*)&s->HL[row][2 * pc] = vhl;
            *(ulonglong2*)&s->HH[row][2 * pc] = vhh;
        }
        __syncthreads();

        // ---- stage 2: horizontal synthesis, PAIR-coarsened (jjp=2u,2u+1 share window) ----
        for (int idx = tid; idx < 19 * 32; idx += 256) {
            int mrow = idx >> 5, u = idx & 31;
            u64 ae = 0, ao = 0, de = 0, dq = 0;
#pragma unroll
            for (int q = 0; q < 4; q++) {
                int ci = u + 4 - q;                        // shifted origin: +1
                u64 vLL = s->LL[mrow][ci], vLH = s->LH[mrow][ci];
                u64 vHL = s->HL[mrow][ci], vHH = s->HH[mrow][ci];
                fma2(ae, lo2[2 * q], vLL);     fma2(ae, hi2[2 * q], vLH);
                fma2(ao, lo2[2 * q + 1], vLL); fma2(ao, hi2[2 * q + 1], vLH);
                fma2(de, lo2[2 * q], vHL);     fma2(de, hi2[2 * q], vHH);
                fma2(dq, lo2[2 * q + 1], vHL); fma2(dq, hi2[2 * q + 1], vHH);
            }
            ulonglong2 va; va.x = ae; va.y = ao;
            ulonglong2 vd; vd.x = de; vd.y = dq;
            *(ulonglong2*)&s->Aq[mrow][2 * u] = va;        // stride 66: 16B aligned
            *(ulonglong2*)&s->Dq[mrow][2 * u] = vd;
        }
        __syncthreads();

        // ---- stage 3: vertical synthesis, row-PAIR coarsened (g2,g2+1 share 3 rows) ----
        for (int idx = tid; idx < 512; idx += 256) {
            int jj = idx & 63, gp = idx >> 6;
            int g2 = gp << 1;
            u64 e0 = 0, o0 = 0, e1 = 0, o1 = 0;
#pragma unroll
            for (int w = 0; w < 5; w++) {
                u64 a = s->Aq[g2 + w][jj], d = s->Dq[g2 + w][jj];
                if (w < 4) {
                    fma2(e0, lo2[6 - 2 * w], a); fma2(e0, hi2[6 - 2 * w], d);
                    fma2(o0, lo2[7 - 2 * w], a); fma2(o0, hi2[7 - 2 * w], d);
                }
                if (w >= 1) {
                    fma2(e1, lo2[8 - 2 * w], a); fma2(e1, hi2[8 - 2 * w], d);
                    fma2(o1, lo2[9 - 2 * w], a); fma2(o1, hi2[9 - 2 * w], d);
                }
            }
            const int gj = j0 + jj;
            const int r0 = i0 + (gp << 2);                 // rows r0..r0+3
            if (outmode == 0) {
                const int gjm = gj & nm;
                dst[(size_t)((r0) & nm) * n + gjm] = e0;
                dst[(size_t)((r0 + 1) & nm) * n + gjm] = o0;
                dst[(size_t)((r0 + 2) & nm) * n + gjm] = e1;
                dst[(size_t)((r0 + 3) & nm) * n + gjm] = o1;
            } else if (outmode == 1) {
                u64* o64 = (u64*)outp;
                int oc = (gj - shift) & MASK0;
                size_t p0 = (size_t)((r0 - shift) & MASK0) * N0 + oc;
                size_t p1 = (size_t)((r0 + 1 - shift) & MASK0) * N0 + oc;
                size_t p2 = (size_t)((r0 + 2 - shift) & MASK0) * N0 + oc;
                size_t p3 = (size_t)((r0 + 3 - shift) & MASK0) * N0 + oc;
                if (p0 < cap) o64[p0] = e0;
                if (p1 < cap) o64[p1] = o0;
                if (p2 < cap) o64[p2] = e1;
                if (p3 < cap) o64[p3] = o1;
            } else {
                float* of = (float*)outp;
                int oc = (gj - shift) & MASK0;
                U64F2 u0, u1, u2, u3;
                u0.u = e0; u1.u = o0; u2.u = e1; u3.u = o1;
                size_t p0 = (size_t)((r0 - shift) & MASK0) * N0 + oc;
                size_t p1 = (size_t)((r0 + 1 - shift) & MASK0) * N0 + oc;
                size_t p2 = (size_t)((r0 + 2 - shift) & MASK0) * N0 + oc;
                size_t p3 = (size_t)((r0 + 3 - shift) & MASK0) * N0 + oc;
                if (p0 < cap) of[p0] = u0.f.x;
                if (p1 < cap) of[p1] = u1.f.x;
                if (p2 < cap) of[p2] = u2.f.x;
                if (p3 < cap) of[p3] = u3.f.x;
            }
        }
        __syncthreads();
    }
}

// ================= single persistent kernel: all 8 phases =================
__global__ void __launch_bounds__(256, 4) wav_all(
    const float* __restrict__ xr, const float* __restrict__ xi,
    void* outp, int shift, int outmode, size_t cap)
{
    __shared__ __align__(16) SmemU sm;

    fwd_level(xr, xi, 4096, shift, nullptr, g_imgA, 0, 1, &sm.f);
    grid_barrier();
    fwd_level(xr, xi, 2048, shift, g_imgA, g_imgB, 0, 0, &sm.f);
    grid_barrier();
    fwd_level(xr, xi, 1024, shift, g_imgB, g_imgA, 0, 0, &sm.f);
    grid_barrier();
    fwd_level(xr, xi, 512, shift, g_imgA, g_imgB, 1, 0, &sm.f);
    grid_barrier();
    inv_level(512, shift, g_imgB, g_imgA, nullptr, 0, 0, &sm.v);
    grid_barrier();
    inv_level(1024, shift, g_imgA, g_imgB, nullptr, 0, 0, &sm.v);
    grid_barrier();
    inv_level(2048, shift, g_imgB, g_imgA, nullptr, 0, 0, &sm.v);
    grid_barrier();
    inv_level(4096, shift, g_imgA, nullptr, outp, outmode, cap, &sm.v);
}

// ---------------- host: numpy default_rng(1000).uniform(-3,3) ----------------
static int compute_shift() {
    const uint32_t INIT_A = 0x43b0d7e5u, MULT_A = 0x931e8875u;
    const uint32_t INIT_B = 0x8b51f9ddu, MULT_B = 0x58f38dedu;
    const uint32_t MIX_L = 0xca01f9ddu, MIX_R = 0x4973f715u;

    uint32_t hc = INIT_A;
    auto hashmix = [&](uint32_t v) -> uint32_t {
        v ^= hc; hc *= MULT_A; v *= hc; v ^= v >> 16; return v;
    };
    auto mix = [&](uint32_t x, uint32_t y) -> uint32_t {
        uint32_t r = MIX_L * x; r ^= MIX_R * y; r ^= r >> 16; return r;
    };

    uint32_t pool[4];
    for (int i = 0; i < 4; i++) pool[i] = hashmix(i == 0 ? 1000u : 0u);
    for (int s = 0; s < 4; s++)
        for (int d = 0; d < 4; d++)
            if (s != d) pool[d] = mix(pool[d], hashmix(pool[s]));

    uint32_t hb = INIT_B;
    uint32_t st[8];
    for (int i = 0; i < 8; i++) {
        uint32_t v = pool[i % 4];
        v ^= hb; hb *= MULT_B; v *= hb; v ^= v >> 16;
        st[i] = v;
    }
    uint64_t w[4];
    for (int i = 0; i < 4; i++)
        w[i] = (uint64_t)st[2 * i] | ((uint64_t)st[2 * i + 1] << 32);

    __uint128_t initstate = ((__uint128_t)w[0] << 64) | w[1];
    __uint128_t initseq = ((__uint128_t)w[2] << 64) | w[3];
    const __uint128_t MULT =
        ((__uint128_t)0x2360ed051fc65da4ULL << 64) | 0x4385df649fccf645ULL;

    __uint128_t inc = (initseq << 1) | 1;
    __uint128_t state = 0;
    state = state * MULT + inc;
    state += initstate;
    state = state * MULT + inc;
    state = state * MULT + inc;
    uint64_t xored = (uint64_t)(state >> 64) ^ (uint64_t)state;
    unsigned rot = (unsigned)(state >> 122) & 63u;
    uint64_t r64 = (xored >> rot) | (xored << ((64u - rot) & 63u));
    double dbl = (double)(r64 >> 11) * (1.0 / 9007199254740992.0);
    double u = -3.0 + 6.0 * dbl;
    return (int)nearbyint(u);
}

// ---------------- launch ----------------
extern "C" void kernel_launch(void* const* d_in, const int* in_sizes, int n_in,
                              void* d_out, int out_size) {
    if (n_in < 2) return;
    if (in_sizes[0] < N0 * N0 || in_sizes[1] < N0 * N0) return;
    const float* xr = (const float*)d_in[0];
    const float* xi = (const float*)d_in[1];

    const size_t capf = (size_t)out_size;
    const bool inter = capf >= (size_t)2 * N0 * N0;
    const int shift = compute_shift();
    const int outmode = inter ? 1 : 2;
    const size_t cap = inter ? capf / 2 : capf;   // u64 units vs float units

    wav_all<<<592, 256>>>(xr, xi, d_out, shift, outmode, cap);
}